// round 11
// baseline (speedup 1.0000x reference)
#include <cuda_runtime.h>
#include <cuda_bf16.h>
#include <cstdint>

// Problem constants (fixed by the reference):
//   N_NODES = 100000, IN_F = 256, OUT_F = 128, N_EDGES = 1600000
// Inputs (metadata order): X_input[f32 N*256], adj_row[i32 E], adj_col[i32 E],
//                          adj_val[f32 E], W[f32 256*128], bias[f32 128]
// Output: f32 [N, 128]

#define MAX_NODES 100000
#define MAX_EDGES 1600000
#define IN_F      256
#define OUT_F     128

// -------------------- static device scratch (no allocs) --------------------
__device__ __align__(16) float g_support[(size_t)MAX_NODES * OUT_F]; // 51.2 MB
__device__ int   g_row_start[MAX_NODES];   // CSR exclusive row offsets
__device__ int   g_row_cnt[MAX_NODES];     // row degrees
__device__ int   g_cursor[MAX_NODES];      // scatter cursors
__device__ int   g_blk_sum[128];           // scan block partials (98 used)
__device__ int   g_ecol[MAX_EDGES];        // CSR column indices
__device__ float g_eval[MAX_EDGES];        // CSR values

// ---------------------------------------------------------------------------
// Kernel 1: SGEMM  S[M,128] = X[M,256] @ W[256,128]
// 128x128 block tile, BK=16, 256 threads.
// Warp grid 4(m) x 2(n) -> warp tile 32x64. Lane grid 4(m) x 8(n).
// Split-half micro-tile: rows rbase+{0..3}, rbase+16+{0..3};
//                        cols cbase+{0..3}, cbase+32+{0..3}.
// => every frag LDS.128 is a contiguous 64B/128B span w/ broadcast:
//    conflict-free (the old tcol*8 mapping was 4-way conflicted).
// Register double-buffering of global tiles hides DRAM tile latency.
// ---------------------------------------------------------------------------
#define BM 128
#define BN 128
#define BK 16
#define NIT (IN_F / BK)      // 16
#define ASTRIDE (BM + 4)

__global__ __launch_bounds__(256, 2)
void gemm_kernel(const float* __restrict__ X, const float* __restrict__ W,
                 float* __restrict__ S, int M) {
    __shared__ float As[BK][ASTRIDE];   // K-major A tile
    __shared__ float Bs[BK][BN];

    const int tid  = threadIdx.x;
    const int row0 = blockIdx.x * BM;
    const int warp = tid >> 5, lane = tid & 31;
    const int warp_m = warp & 3, warp_n = warp >> 2;       // 4 x 2 warps
    const int lane_m = lane & 3, lane_n = lane >> 2;       // 4 x 8 lanes
    const int rbase = warp_m * 32 + lane_m * 4;
    const int cbase = warp_n * 64 + lane_n * 4;

    // staging indices (2 float4 of A + 2 float4 of B per thread per tile)
    const int a_r0 = tid >> 2;           // 0..63
    const int a_c  = (tid & 3) * 4;      // k-chunk within BK
    const int b_r0 = tid >> 5;           // 0..7
    const int b_c  = (tid & 31) * 4;

    // clamped global rows (duplicate loads for OOB, never stored)
    int gr0 = row0 + a_r0;       if (gr0 >= M) gr0 = M - 1;
    int gr1 = row0 + a_r0 + 64;  if (gr1 >= M) gr1 = M - 1;

    float acc[8][8];
#pragma unroll
    for (int i = 0; i < 8; i++)
#pragma unroll
        for (int j = 0; j < 8; j++) acc[i][j] = 0.0f;

    float4 ra0, ra1, rb0, rb1;

    auto ldg_tile = [&](int k0, float4& A0, float4& A1, float4& B0, float4& B1) {
        A0 = *(const float4*)(X + (size_t)gr0 * IN_F + k0 + a_c);
        A1 = *(const float4*)(X + (size_t)gr1 * IN_F + k0 + a_c);
        B0 = *(const float4*)(W + (size_t)(k0 + b_r0)     * OUT_F + b_c);
        B1 = *(const float4*)(W + (size_t)(k0 + b_r0 + 8) * OUT_F + b_c);
    };
    auto sts_tile = [&](const float4& A0, const float4& A1,
                        const float4& B0, const float4& B1) {
        As[a_c + 0][a_r0] = A0.x;  As[a_c + 1][a_r0] = A0.y;
        As[a_c + 2][a_r0] = A0.z;  As[a_c + 3][a_r0] = A0.w;
        As[a_c + 0][a_r0 + 64] = A1.x;  As[a_c + 1][a_r0 + 64] = A1.y;
        As[a_c + 2][a_r0 + 64] = A1.z;  As[a_c + 3][a_r0 + 64] = A1.w;
        *(float4*)&Bs[b_r0][b_c]     = B0;
        *(float4*)&Bs[b_r0 + 8][b_c] = B1;
    };

    // prologue: tile 0 into smem
    ldg_tile(0, ra0, ra1, rb0, rb1);
    sts_tile(ra0, ra1, rb0, rb1);
    __syncthreads();

    for (int it = 0; it < NIT; ++it) {
        float4 na0, na1, nb0, nb1;
        if (it + 1 < NIT)
            ldg_tile((it + 1) * BK, na0, na1, nb0, nb1);  // overlap with compute

#pragma unroll
        for (int k = 0; k < BK; k++) {
            float4 a0 = *(const float4*)&As[k][rbase];
            float4 a1 = *(const float4*)&As[k][rbase + 16];
            float4 b0 = *(const float4*)&Bs[k][cbase];
            float4 b1 = *(const float4*)&Bs[k][cbase + 32];
            float av[8] = {a0.x, a0.y, a0.z, a0.w, a1.x, a1.y, a1.z, a1.w};
            float bv[8] = {b0.x, b0.y, b0.z, b0.w, b1.x, b1.y, b1.z, b1.w};
#pragma unroll
            for (int i = 0; i < 8; i++)
#pragma unroll
                for (int j = 0; j < 8; j++)
                    acc[i][j] = fmaf(av[i], bv[j], acc[i][j]);
        }

        if (it + 1 < NIT) {
            __syncthreads();
            sts_tile(na0, na1, nb0, nb1);
            __syncthreads();
        }
    }

    // store: split-half rows/cols
#pragma unroll
    for (int i = 0; i < 8; i++) {
        int r = row0 + rbase + (i < 4 ? i : 12 + i);   // +{0..3}, +16+{0..3}
        if (r < M) {
            float4 o0 = make_float4(acc[i][0], acc[i][1], acc[i][2], acc[i][3]);
            float4 o1 = make_float4(acc[i][4], acc[i][5], acc[i][6], acc[i][7]);
            float* dst = S + (size_t)r * OUT_F;
            *(float4*)(dst + cbase)      = o0;
            *(float4*)(dst + cbase + 32) = o1;
        }
    }
}

// ---------------------------------------------------------------------------
// CSR build (per call; deterministic up to within-row edge order, which only
// perturbs fp32 summation order at ~1e-7 — same property the previous
// atomic-scatter kernel had).
// ---------------------------------------------------------------------------
__global__ void zero_kernel(int N) {
    int i = blockIdx.x * blockDim.x + threadIdx.x;
    if (i < N) { g_row_cnt[i] = 0; g_cursor[i] = 0; }
}

__global__ void hist_kernel(const int* __restrict__ adj_row, int E) {
    int e = blockIdx.x * blockDim.x + threadIdx.x;
    if (e < E) atomicAdd(&g_row_cnt[adj_row[e]], 1);
}

// scan1: per-1024 chunk exclusive scan + chunk totals
__global__ void scan1_kernel(int N) {
    __shared__ int s[1024];
    int t = threadIdx.x;
    int i = blockIdx.x * 1024 + t;
    int v = (i < N) ? g_row_cnt[i] : 0;
    s[t] = v;
    __syncthreads();
#pragma unroll
    for (int off = 1; off < 1024; off <<= 1) {
        int x = (t >= off) ? s[t - off] : 0;
        __syncthreads();
        s[t] += x;
        __syncthreads();
    }
    if (i < N) g_row_start[i] = s[t] - v;     // exclusive within chunk
    if (t == 1023) g_blk_sum[blockIdx.x] = s[1023];
}

// scan2: exclusive scan of chunk totals (tiny; single thread)
__global__ void scan2_kernel(int nblk) {
    if (threadIdx.x == 0 && blockIdx.x == 0) {
        int run = 0;
        for (int b = 0; b < nblk; b++) {
            int t = g_blk_sum[b];
            g_blk_sum[b] = run;
            run += t;
        }
    }
}

__global__ void scan3_kernel(int N) {
    int i = blockIdx.x * blockDim.x + threadIdx.x;
    if (i < N) g_row_start[i] += g_blk_sum[i >> 10];
}

__global__ void scatter_kernel(const int* __restrict__ adj_row,
                               const int* __restrict__ adj_col,
                               const float* __restrict__ adj_val, int E) {
    int e = blockIdx.x * blockDim.x + threadIdx.x;
    if (e < E) {
        int r = adj_row[e];
        int pos = g_row_start[r] + atomicAdd(&g_cursor[r], 1);
        g_ecol[pos] = adj_col[e];
        g_eval[pos] = adj_val[e];
    }
}

// ---------------------------------------------------------------------------
// Kernel: CSR SpMM, warp per output row. Each lane owns one float4 (4 cols)
// of the 128-wide row; row accumulated in registers, written ONCE (kills the
// 819 MB atomic write stream). Gathers are L2-resident (support=51.2MB<L2).
// Bias folded in -> init kernel eliminated.
// ---------------------------------------------------------------------------
__global__ __launch_bounds__(256)
void spmm_csr_kernel(const float* __restrict__ S, const float* __restrict__ bias,
                     float* __restrict__ out, int N) {
    const int w    = (blockIdx.x * blockDim.x + threadIdx.x) >> 5;
    const int lane = threadIdx.x & 31;
    if (w >= N) return;

    const int start = g_row_start[w];
    const int deg   = g_row_cnt[w];

    float4 acc = __ldg((const float4*)bias + lane);

    int i = 0;
    for (; i + 4 <= deg; i += 4) {
        int   c0 = __ldg(g_ecol + start + i + 0);
        int   c1 = __ldg(g_ecol + start + i + 1);
        int   c2 = __ldg(g_ecol + start + i + 2);
        int   c3 = __ldg(g_ecol + start + i + 3);
        float v0 = __ldg(g_eval + start + i + 0);
        float v1 = __ldg(g_eval + start + i + 1);
        float v2 = __ldg(g_eval + start + i + 2);
        float v3 = __ldg(g_eval + start + i + 3);
        float4 s0 = __ldg((const float4*)(S + (size_t)c0 * OUT_F) + lane);
        float4 s1 = __ldg((const float4*)(S + (size_t)c1 * OUT_F) + lane);
        float4 s2 = __ldg((const float4*)(S + (size_t)c2 * OUT_F) + lane);
        float4 s3 = __ldg((const float4*)(S + (size_t)c3 * OUT_F) + lane);
        acc.x = fmaf(v0, s0.x, acc.x); acc.y = fmaf(v0, s0.y, acc.y);
        acc.z = fmaf(v0, s0.z, acc.z); acc.w = fmaf(v0, s0.w, acc.w);
        acc.x = fmaf(v1, s1.x, acc.x); acc.y = fmaf(v1, s1.y, acc.y);
        acc.z = fmaf(v1, s1.z, acc.z); acc.w = fmaf(v1, s1.w, acc.w);
        acc.x = fmaf(v2, s2.x, acc.x); acc.y = fmaf(v2, s2.y, acc.y);
        acc.z = fmaf(v2, s2.z, acc.z); acc.w = fmaf(v2, s2.w, acc.w);
        acc.x = fmaf(v3, s3.x, acc.x); acc.y = fmaf(v3, s3.y, acc.y);
        acc.z = fmaf(v3, s3.z, acc.z); acc.w = fmaf(v3, s3.w, acc.w);
    }
    for (; i < deg; ++i) {
        int   c = __ldg(g_ecol + start + i);
        float v = __ldg(g_eval + start + i);
        float4 s = __ldg((const float4*)(S + (size_t)c * OUT_F) + lane);
        acc.x = fmaf(v, s.x, acc.x); acc.y = fmaf(v, s.y, acc.y);
        acc.z = fmaf(v, s.z, acc.z); acc.w = fmaf(v, s.w, acc.w);
    }

    ((float4*)(out + (size_t)w * OUT_F))[lane] = acc;
}

// ---------------------------------------------------------------------------
// Launch sequence (single stream; all graph-capturable).
// ---------------------------------------------------------------------------
extern "C" void kernel_launch(void* const* d_in, const int* in_sizes, int n_in,
                              void* d_out, int out_size) {
    const float* X    = (const float*)d_in[0];
    const int*   arow = (const int*)  d_in[1];
    const int*   acol = (const int*)  d_in[2];
    const float* aval = (const float*)d_in[3];
    const float* W    = (const float*)d_in[4];
    const float* bias = (const float*)d_in[5];
    float*       out  = (float*)d_out;

    const int M = in_sizes[0] / IN_F;   // 100000
    const int E = in_sizes[1];          // 1600000

    static float* S = nullptr;
    if (S == nullptr) {
        void* p = nullptr;
        cudaGetSymbolAddress(&p, g_support);
        S = (float*)p;
    }

    // 1) support = X @ W
    gemm_kernel<<<(M + BM - 1) / BM, 256>>>(X, W, S, M);

    // 2) CSR build (independent of GEMM; serialized on stream, cheap)
    zero_kernel<<<(M + 255) / 256, 256>>>(M);
    hist_kernel<<<(E + 255) / 256, 256>>>(arow, E);
    const int nblk = (M + 1023) / 1024;
    scan1_kernel<<<nblk, 1024>>>(M);
    scan2_kernel<<<1, 32>>>(nblk);
    scan3_kernel<<<(M + 255) / 256, 256>>>(M);
    scatter_kernel<<<(E + 255) / 256, 256>>>(arow, acol, aval, E);

    // 3) out[r,:] = bias + sum_e val_e * support[col_e, :]
    const int nwarps  = M;
    const int nblocks = (nwarps + 7) / 8;   // 8 warps per 256-thread block
    spmm_csr_kernel<<<nblocks, 256>>>(S, bias, out, M);
}